// round 1
// baseline (speedup 1.0000x reference)
#include <cuda_runtime.h>
#include <cuda_bf16.h>
#include <cstdint>

// EMA filter: out[d,l] = sum_n p[d,n] * q[d,n]^l * gamma[d,n]
// D=2048, N=16, L=4096. Strategy: geometric recurrence with packed f32x2 math.
// One block per d (2048 blocks, 128 threads). Thread t owns l = t + 128*i.
// pow_n(l+128) = pow_n(l) * q_n^128.  All heavy math in fma.rn.f32x2 /
// mul.rn.f32x2 (Blackwell packed fp32 pipe, 2x FLOP per inst).

#define D_DIM 2048
#define N_DIM 16
#define L_DIM 4096
#define TPB   128
#define ITERS (L_DIM / TPB)   // 32
#define NP    (N_DIM / 2)     // 8 packed pairs

__device__ __forceinline__ unsigned long long pack2(float lo, float hi) {
    unsigned long long r;
    asm("mov.b64 %0, {%1, %2};" : "=l"(r) : "f"(lo), "f"(hi));
    return r;
}
__device__ __forceinline__ void unpack2(unsigned long long v, float& lo, float& hi) {
    asm("mov.b64 {%0, %1}, %2;" : "=f"(lo), "=f"(hi) : "l"(v));
}
__device__ __forceinline__ unsigned long long fma2(unsigned long long a,
                                                   unsigned long long b,
                                                   unsigned long long c) {
    unsigned long long r;
    asm("fma.rn.f32x2 %0, %1, %2, %3;" : "=l"(r) : "l"(a), "l"(b), "l"(c));
    return r;
}
__device__ __forceinline__ unsigned long long mul2(unsigned long long a,
                                                   unsigned long long b) {
    unsigned long long r;
    asm("mul.rn.f32x2 %0, %1, %2;" : "=l"(r) : "l"(a), "l"(b));
    return r;
}
__device__ __forceinline__ unsigned long long add2(unsigned long long a,
                                                   unsigned long long b) {
    unsigned long long r;
    asm("add.rn.f32x2 %0, %1, %2;" : "=l"(r) : "l"(a), "l"(b));
    return r;
}

__global__ __launch_bounds__(TPB, 8)
void ema_filter_kernel(const float* __restrict__ p,
                       const float* __restrict__ q,
                       const float* __restrict__ gamma,
                       float* __restrict__ out) {
    __shared__ float s_c[N_DIM];    // p * gamma
    __shared__ float s_lq[N_DIM];   // log2(q)
    __shared__ float s_m[N_DIM];    // q^TPB (stride multiplier)

    const int d   = blockIdx.x;
    const int tid = threadIdx.x;

    if (tid < N_DIM) {
        const int idx = d * N_DIM + tid;
        float qv = q[idx];
        float lq = __log2f(qv);
        s_lq[tid] = lq;
        s_c[tid]  = p[idx] * gamma[idx];
        s_m[tid]  = exp2f((float)TPB * lq);
    }
    __syncthreads();

    // Per-thread packed state
    unsigned long long c2[NP], m2[NP], w2[NP];
    const float t = (float)tid;
#pragma unroll
    for (int j = 0; j < NP; j++) {
        float p0 = exp2f(t * s_lq[2 * j]);
        float p1 = exp2f(t * s_lq[2 * j + 1]);
        w2[j] = pack2(p0, p1);
        c2[j] = pack2(s_c[2 * j], s_c[2 * j + 1]);
        m2[j] = pack2(s_m[2 * j], s_m[2 * j + 1]);
    }

    float* o = out + (size_t)d * L_DIM + tid;

#pragma unroll
    for (int i = 0; i < ITERS; i++) {
        // two independent fma chains (depth 4 each) for ILP
        unsigned long long a0 = 0ull, a1 = 0ull;
#pragma unroll
        for (int j = 0; j < NP; j += 2) {
            a0 = fma2(c2[j],     w2[j],     a0);
            a1 = fma2(c2[j + 1], w2[j + 1], a1);
        }
        a0 = add2(a0, a1);
        float lo, hi;
        unpack2(a0, lo, hi);
        o[i * TPB] = lo + hi;

        // advance powers by q^128
#pragma unroll
        for (int j = 0; j < NP; j++) w2[j] = mul2(w2[j], m2[j]);
    }
}

extern "C" void kernel_launch(void* const* d_in, const int* in_sizes, int n_in,
                              void* d_out, int out_size) {
    const float* p     = (const float*)d_in[0];
    const float* q     = (const float*)d_in[1];
    const float* gamma = (const float*)d_in[2];
    float* out = (float*)d_out;
    ema_filter_kernel<<<D_DIM, TPB>>>(p, q, gamma, out);
}

// round 2
// speedup vs baseline: 1.0744x; 1.0744x over previous
#include <cuda_runtime.h>
#include <cuda_bf16.h>
#include <cstdint>

// EMA filter: out[d,l] = sum_n p[d,n] * q[d,n]^l * gamma[d,n]
// D=2048, N=16, L=4096.
// Geometric recurrence, packed f32x2 math, k=2 output folding:
// one power state w2 = q^(t+128i) (pair over n) serves BOTH out[t+128i]
// (coeff c) and out[t+128i+2048] (coeff c*q^2048), halving the mul2
// advance cost per output.

#define D_DIM 2048
#define N_DIM 16
#define L_DIM 4096
#define TPB   128
#define HALF_L (L_DIM / 2)        // 2048
#define ITERS (HALF_L / TPB)      // 16
#define NP    (N_DIM / 2)         // 8 packed n-pairs

__device__ __forceinline__ unsigned long long pack2(float lo, float hi) {
    unsigned long long r;
    asm("mov.b64 %0, {%1, %2};" : "=l"(r) : "f"(lo), "f"(hi));
    return r;
}
__device__ __forceinline__ void unpack2(unsigned long long v, float& lo, float& hi) {
    asm("mov.b64 {%0, %1}, %2;" : "=f"(lo), "=f"(hi) : "l"(v));
}
__device__ __forceinline__ unsigned long long fma2(unsigned long long a,
                                                   unsigned long long b,
                                                   unsigned long long c) {
    unsigned long long r;
    asm("fma.rn.f32x2 %0, %1, %2, %3;" : "=l"(r) : "l"(a), "l"(b), "l"(c));
    return r;
}
__device__ __forceinline__ unsigned long long mul2(unsigned long long a,
                                                   unsigned long long b) {
    unsigned long long r;
    asm("mul.rn.f32x2 %0, %1, %2;" : "=l"(r) : "l"(a), "l"(b));
    return r;
}
__device__ __forceinline__ unsigned long long add2(unsigned long long a,
                                                   unsigned long long b) {
    unsigned long long r;
    asm("add.rn.f32x2 %0, %1, %2;" : "=l"(r) : "l"(a), "l"(b));
    return r;
}

__global__ __launch_bounds__(TPB, 6)
void ema_filter_kernel(const float* __restrict__ p,
                       const float* __restrict__ q,
                       const float* __restrict__ gamma,
                       float* __restrict__ out) {
    __shared__ float s_c[N_DIM];    // p * gamma
    __shared__ float s_ck[N_DIM];   // p * gamma * q^2048
    __shared__ float s_lq[N_DIM];   // log2(q)
    __shared__ float s_m[N_DIM];    // q^128 (stride multiplier)

    const int d   = blockIdx.x;
    const int tid = threadIdx.x;

    if (tid < N_DIM) {
        const int idx = d * N_DIM + tid;
        float qv = q[idx];
        float lq = __log2f(qv);
        float c  = p[idx] * gamma[idx];
        s_lq[tid] = lq;
        s_c[tid]  = c;
        s_m[tid]  = exp2f((float)TPB * lq);
        s_ck[tid] = c * exp2f((float)HALF_L * lq);  // underflow->0 matches ref
    }
    __syncthreads();

    // Per-thread packed state (pairs over n)
    unsigned long long c2[NP], ck2[NP], m2[NP], w2[NP];
    const float t = (float)tid;
#pragma unroll
    for (int j = 0; j < NP; j++) {
        float p0 = exp2f(t * s_lq[2 * j]);
        float p1 = exp2f(t * s_lq[2 * j + 1]);
        w2[j]  = pack2(p0, p1);
        c2[j]  = pack2(s_c[2 * j],  s_c[2 * j + 1]);
        ck2[j] = pack2(s_ck[2 * j], s_ck[2 * j + 1]);
        m2[j]  = pack2(s_m[2 * j],  s_m[2 * j + 1]);
    }

    float* o = out + (size_t)d * L_DIM + tid;

#pragma unroll
    for (int i = 0; i < ITERS; i++) {
        // 4 independent fma chains (depth 4 each): two outputs per power state
        unsigned long long a0 = 0ull, a1 = 0ull, b0 = 0ull, b1 = 0ull;
#pragma unroll
        for (int j = 0; j < NP; j += 2) {
            a0 = fma2(c2[j],      w2[j],     a0);
            a1 = fma2(c2[j + 1],  w2[j + 1], a1);
            b0 = fma2(ck2[j],     w2[j],     b0);
            b1 = fma2(ck2[j + 1], w2[j + 1], b1);
        }
        a0 = add2(a0, a1);
        b0 = add2(b0, b1);
        float alo, ahi, blo, bhi;
        unpack2(a0, alo, ahi);
        unpack2(b0, blo, bhi);
        o[i * TPB]          = alo + ahi;
        o[i * TPB + HALF_L] = blo + bhi;

        // advance powers by q^128 (amortized over 2 outputs)
#pragma unroll
        for (int j = 0; j < NP; j++) w2[j] = mul2(w2[j], m2[j]);
    }
}

extern "C" void kernel_launch(void* const* d_in, const int* in_sizes, int n_in,
                              void* d_out, int out_size) {
    const float* p     = (const float*)d_in[0];
    const float* q     = (const float*)d_in[1];
    const float* gamma = (const float*)d_in[2];
    float* out = (float*)d_out;
    ema_filter_kernel<<<D_DIM, TPB>>>(p, q, gamma, out);
}

// round 3
// speedup vs baseline: 1.4657x; 1.3642x over previous
#include <cuda_runtime.h>
#include <cuda_bf16.h>
#include <cstdint>

// EMA filter: out[d,l] = sum_n p[d,n] * q[d,n]^l * gamma[d,n]
// D=2048, N=16, L=4096.
// Key facts from profiling: kernel is RF-bank issue-bound on f32x2 ops
// (rt=3/SMSP), so the only wins are fewer slot-cycles per output.
// Key math fact: q <= 0.95 => q^l underflows fp32 for l > 150/(-log2 q),
// so out[d, l] == 0 (reference expf underflows identically) beyond a
// per-d active length L_act <= ~2048. Compute only [0, L_act) with the
// k=2-folded geometric recurrence (fold offset H = L_act/2), zero-fill
// the rest with wide stores.

#define D_DIM 2048
#define N_DIM 16
#define L_DIM 4096
#define TPB   128
#define NP    (N_DIM / 2)   // 8 packed n-pairs

__device__ __forceinline__ unsigned long long pack2(float lo, float hi) {
    unsigned long long r;
    asm("mov.b64 %0, {%1, %2};" : "=l"(r) : "f"(lo), "f"(hi));
    return r;
}
__device__ __forceinline__ void unpack2(unsigned long long v, float& lo, float& hi) {
    asm("mov.b64 {%0, %1}, %2;" : "=f"(lo), "=f"(hi) : "l"(v));
}
__device__ __forceinline__ unsigned long long fma2(unsigned long long a,
                                                   unsigned long long b,
                                                   unsigned long long c) {
    unsigned long long r;
    asm("fma.rn.f32x2 %0, %1, %2, %3;" : "=l"(r) : "l"(a), "l"(b), "l"(c));
    return r;
}
__device__ __forceinline__ unsigned long long mul2(unsigned long long a,
                                                   unsigned long long b) {
    unsigned long long r;
    asm("mul.rn.f32x2 %0, %1, %2;" : "=l"(r) : "l"(a), "l"(b));
    return r;
}
__device__ __forceinline__ unsigned long long add2(unsigned long long a,
                                                   unsigned long long b) {
    unsigned long long r;
    asm("add.rn.f32x2 %0, %1, %2;" : "=l"(r) : "l"(a), "l"(b));
    return r;
}

__global__ __launch_bounds__(TPB, 6)
void ema_filter_kernel(const float* __restrict__ p,
                       const float* __restrict__ q,
                       const float* __restrict__ gamma,
                       float* __restrict__ out) {
    __shared__ float s_c[N_DIM];    // p * gamma
    __shared__ float s_ck[N_DIM];   // p * gamma * q^H
    __shared__ float s_lq[N_DIM];   // log2(q)
    __shared__ float s_m[N_DIM];    // q^128 (stride multiplier)
    __shared__ float s_ls[N_DIM];   // per-n active length l*

    const int d   = blockIdx.x;
    const int tid = threadIdx.x;

    if (tid < N_DIM) {
        const int idx = d * N_DIM + tid;
        float qv = q[idx];
        float lq = __log2f(qv);
        float c  = p[idx] * gamma[idx];
        s_lq[tid] = lq;
        s_c[tid]  = c;
        s_m[tid]  = exp2f(128.0f * lq);
        // term n is exactly 0 (fp32 underflow, matching reference expf)
        // for l * lq < -150. Guard lq >= 0 (q >= 1): never dead.
        s_ls[tid] = (lq < 0.0f) ? (150.0f / (-lq)) : 4096.0f;
    }
    __syncthreads();

    // All threads compute the per-d active length (uniform across block).
    float mx = s_ls[0];
#pragma unroll
    for (int n = 1; n < N_DIM; n++) mx = fmaxf(mx, s_ls[n]);
    mx = fminf(mx, 4096.0f);
    int Li = ((int)mx + 1 + 255) & ~255;   // ceil, round up to 256
    if (Li > L_DIM) Li = L_DIM;
    const int H     = Li >> 1;             // fold offset (multiple of 128)
    const int iters = H >> 7;              // 1..16

    if (tid < N_DIM) {
        // coefficient for the upper fold half: c * q^H (underflow->0 ok)
        s_ck[tid] = s_c[tid] * exp2f((float)H * s_lq[tid]);
    }
    __syncthreads();

    // Per-thread packed state (pairs over n)
    unsigned long long c2[NP], ck2[NP], m2[NP], w2[NP];
    const float t = (float)tid;
#pragma unroll
    for (int j = 0; j < NP; j++) {
        float p0 = exp2f(t * s_lq[2 * j]);
        float p1 = exp2f(t * s_lq[2 * j + 1]);
        w2[j]  = pack2(p0, p1);
        c2[j]  = pack2(s_c[2 * j],  s_c[2 * j + 1]);
        ck2[j] = pack2(s_ck[2 * j], s_ck[2 * j + 1]);
        m2[j]  = pack2(s_m[2 * j],  s_m[2 * j + 1]);
    }

    float* o = out + (size_t)d * L_DIM + tid;

#pragma unroll 4
    for (int i = 0; i < iters; i++) {
        // 4 independent fma chains: two outputs per power state
        unsigned long long a0 = 0ull, a1 = 0ull, b0 = 0ull, b1 = 0ull;
#pragma unroll
        for (int j = 0; j < NP; j += 2) {
            a0 = fma2(c2[j],      w2[j],     a0);
            a1 = fma2(c2[j + 1],  w2[j + 1], a1);
            b0 = fma2(ck2[j],     w2[j],     b0);
            b1 = fma2(ck2[j + 1], w2[j + 1], b1);
        }
        a0 = add2(a0, a1);
        b0 = add2(b0, b1);
        float alo, ahi, blo, bhi;
        unpack2(a0, alo, ahi);
        unpack2(b0, blo, bhi);
        o[i * TPB]     = alo + ahi;
        o[i * TPB + H] = blo + bhi;

        // advance powers by q^128 (amortized over 2 outputs)
#pragma unroll
        for (int j = 0; j < NP; j++) w2[j] = mul2(w2[j], m2[j]);
    }

    // Zero-fill [Li, 4096) with 16B stores (Li is a multiple of 256).
    float4 z = make_float4(0.0f, 0.0f, 0.0f, 0.0f);
    float4* o4 = (float4*)(out + (size_t)d * L_DIM);
    for (int j4 = (Li >> 2) + tid; j4 < (L_DIM >> 2); j4 += TPB) {
        o4[j4] = z;
    }
}

extern "C" void kernel_launch(void* const* d_in, const int* in_sizes, int n_in,
                              void* d_out, int out_size) {
    const float* p     = (const float*)d_in[0];
    const float* q     = (const float*)d_in[1];
    const float* gamma = (const float*)d_in[2];
    float* out = (float*)d_out;
    ema_filter_kernel<<<D_DIM, TPB>>>(p, q, gamma, out);
}